// round 8
// baseline (speedup 1.0000x reference)
#include <cuda_runtime.h>
#include <math.h>
#include <stdint.h>

#define T_  64
#define B_  64
#define S_  128
#define E_  512
#define H_  1024
#define EH_ 1536
#define BH_ (B_*H_)
#define TBH_ ((size_t)T_*B_*H_)
#define SPLIT_ 8

// ---------------- scratch (device globals; zero-init) ----------------
__device__ __align__(16) float g_wih0[(size_t)4*H_*EH_];
__device__ __align__(16) float g_whh0[(size_t)4*H_*H_];
__device__ __align__(16) float g_wih1[(size_t)4*H_*H_];
__device__ __align__(16) float g_whh1[(size_t)4*H_*H_];
__device__ __align__(16) float g_wa[(size_t)H_*H_];
__device__ __align__(16) float g_wout[(size_t)H_*2*H_];
__device__ __align__(16) float g_inp[(size_t)T_*B_*E_];
__device__ __align__(16) float g_hb0[2*BH_];     // layer0 h ping-pong (tf32-rounded)
__device__ __align__(16) float g_hb1[2*BH_];
__device__ __align__(16) float g_hraw0[BH_];     // unrounded h for hF
__device__ __align__(16) float g_hraw1[BH_];
__device__ __align__(16) float g_cb0[BH_];
__device__ __align__(16) float g_cb1[BH_];
__device__ __align__(16) float g_q[BH_];         // h1 @ Wa^T
__device__ __align__(16) float g_oh1[BH_];       // h1 @ WoutR^T (pre-tanh partial)
__device__ __align__(16) float g_cvec[BH_];      // tf32-rounded
__device__ __align__(16) float g_feed[BH_];      // tf32-rounded tanh outputs
__device__ __align__(16) float g_scores[B_*S_];
__device__ __align__(16) float g_part[(size_t)256*8192];  // split-K partials (64x128/CTA)
__device__ int g_cnt[64];                        // split-K arrival counters
__device__ __align__(16) float g_zeros[BH_];     // never written -> 0

__device__ __forceinline__ float sigf(float x) { return 1.f / (1.f + expf(-x)); }

__device__ __forceinline__ float to_tf32(float x) {
    uint32_t r;
    asm("cvt.rna.tf32.f32 %0, %1;" : "=r"(r) : "f"(x));
    return __uint_as_float(r);
}

__device__ __forceinline__ void cp16(float* dst, const float* src) {
    unsigned s = (unsigned)__cvta_generic_to_shared(dst);
    asm volatile("cp.async.cg.shared.global [%0], [%1], 16;\n" :: "r"(s), "l"(src));
}

__device__ __forceinline__ void mma8(float* c, const uint32_t* a, const uint32_t* b) {
    asm volatile(
        "mma.sync.aligned.m16n8k8.row.col.f32.tf32.tf32.f32 "
        "{%0,%1,%2,%3}, {%4,%5,%6,%7}, {%8,%9}, {%0,%1,%2,%3};\n"
        : "+f"(c[0]), "+f"(c[1]), "+f"(c[2]), "+f"(c[3])
        : "r"(a[0]), "r"(a[1]), "r"(a[2]), "r"(a[3]), "r"(b[0]), "r"(b[1]));
}

// ---------------- prep kernels ----------------
__global__ __launch_bounds__(512) void prep_weights(
    const float* __restrict__ wih0, const float* __restrict__ whh0,
    const float* __restrict__ wih1, const float* __restrict__ whh1,
    const float* __restrict__ wa,   const float* __restrict__ wout) {
    const size_t n0 = (size_t)4 * H_ * EH_;
    const size_t n1 = (size_t)4 * H_ * H_;
    const size_t n2 = (size_t)H_ * H_;
    const size_t n3 = (size_t)H_ * 2 * H_;
    const size_t tot = n0 + 3 * n1 + n2 + n3;
    for (size_t i = (size_t)blockIdx.x * blockDim.x + threadIdx.x; i < tot;
         i += (size_t)gridDim.x * blockDim.x) {
        size_t j = i; float v; float* d;
        if (j < n0) { v = wih0[j]; d = g_wih0 + j; }
        else { j -= n0;
        if (j < n1) { v = whh0[j]; d = g_whh0 + j; }
        else { j -= n1;
        if (j < n1) { v = wih1[j]; d = g_wih1 + j; }
        else { j -= n1;
        if (j < n1) { v = whh1[j]; d = g_whh1 + j; }
        else { j -= n1;
        if (j < n2) { v = wa[j];   d = g_wa + j; }
        else { j -= n2; v = wout[j]; d = g_wout + j; } } } } }
        *d = to_tf32(v);
    }
}

__global__ __launch_bounds__(512) void prep_state(const float* __restrict__ inp,
                                                  const float* __restrict__ h0,
                                                  const float* __restrict__ c0) {
    const size_t ninp = (size_t)T_ * B_ * E_;
    const size_t tot = ninp + 2 * BH_;
    for (size_t i = (size_t)blockIdx.x * blockDim.x + threadIdx.x; i < tot;
         i += (size_t)gridDim.x * blockDim.x) {
        if (i < ninp) g_inp[i] = to_tf32(inp[i]);
        else {
            size_t j = i - ninp;
            if (j < BH_) { g_hb0[j] = to_tf32(h0[j]); g_cb0[j] = c0[j]; }
            else { j -= BH_; g_hb1[j] = to_tf32(h0[BH_ + j]); g_cb1[j] = c0[BH_ + j]; }
        }
    }
}

// ---------------- split-K GEMM, tile 64 x 128, last-CTA epilogue ----------------
// C(64 x 128 cols) = sum_seg A_seg(64,K) @ W_seg(cols,K)^T, tf32 mma, fp32 acc.
// grid = NGRP * SPLIT_. 256 threads, 8 warps as 2(m) x 4(n): warp tile 32x32.
// mode 1: cols {gate*H + n0 + j}, n0=grp*32, j<32 per gate; LSTM cell epilogue.
// mode 0: cols n0..n0+127 (n0=grp*128); C += addend(cprev); tanh -> hout + g_feed.
// mode 2: plain store -> hout.
// mode 3: grp<8 -> q cols (W0), grp>=8 -> oh1 cols (W1, col-1024); plain stores.
#define STRD_ 36
#define STGA_ (64*STRD_)        // A region: 2304 floats
#define STGF_ (192*STRD_)       // stage: A 64x36 + W 128x36 = 6912 floats
#define NSTG_ 4
__global__ __launch_bounds__(256) void gemm_kernel(
    const float* __restrict__ A0, int lda0, const float* __restrict__ W0, int ldw0, int kt0,
    const float* __restrict__ A1, int lda1, const float* __restrict__ W1, int ldw1, int kt1,
    const float* __restrict__ A2, int lda2, const float* __restrict__ W2, int ldw2, int kt2,
    int mode,
    const float* __restrict__ bi, const float* __restrict__ bh,
    const float* __restrict__ cprev, float* __restrict__ cout,
    float* __restrict__ hout, float* __restrict__ hraw) {

    extern __shared__ __align__(16) float sm[];   // NSTG_ * STGF_ floats

    const int tid = threadIdx.x;
    const int w = tid >> 5, lane = tid & 31;
    const int wm = w >> 2, wn = w & 3;            // 2 x 4 warp grid
    const int g8 = lane >> 2, tg = lane & 3;
    const int grp = blockIdx.x / SPLIT_;
    const int sk  = blockIdx.x % SPLIT_;
    const int n0  = grp * (mode == 1 ? 32 : 128);

    // mode-3 uniform per-CTA weight select
    const float* Wsel = W0; int lwsel = ldw0; int nb = n0;
    if (mode == 3 && grp >= 8) { Wsel = W1; lwsel = ldw1; nb = n0 - 1024; }

    const int tot = kt0 + kt1 + kt2;
    const int cpk = tot / SPLIT_;
    const int cbase = sk * cpk;

    // copy map: A 512 chunks (2/thread), W 1024 chunks (4/thread), 16B each
    int rA[2], cA[2];
#pragma unroll
    for (int j = 0; j < 2; j++) {
        int q = j * 256 + tid;
        rA[j] = q >> 3; cA[j] = (q & 7) * 4;
    }
    int rW[4], cW[4], wrW[4];
#pragma unroll
    for (int j = 0; j < 4; j++) {
        int q = j * 256 + tid;
        rW[j] = q >> 3; cW[j] = (q & 7) * 4;
        wrW[j] = (mode == 1) ? ((rW[j] >> 5) * H_ + n0 + (rW[j] & 31)) : (nb + rW[j]);
    }

    auto issue = [&](int c, int buf) {
        const float* Ab; const float* Wb; int la, lw, ko;
        if (c < kt0)            { Ab = A0; Wb = W0; la = lda0; lw = ldw0; ko = c * 32; }
        else if (c < kt0 + kt1) { Ab = A1; Wb = W1; la = lda1; lw = ldw1; ko = (c - kt0) * 32; }
        else                    { Ab = A2; Wb = W2; la = lda2; lw = ldw2; ko = (c - kt0 - kt1) * 32; }
        if (mode == 3) { Wb = Wsel; lw = lwsel; }
        float* st = sm + buf * STGF_;
#pragma unroll
        for (int j = 0; j < 2; j++)
            cp16(st + rA[j] * STRD_ + cA[j], Ab + (size_t)rA[j] * la + ko + cA[j]);
#pragma unroll
        for (int j = 0; j < 4; j++)
            cp16(st + STGA_ + rW[j] * STRD_ + cW[j], Wb + (size_t)wrW[j] * lw + ko + cW[j]);
        asm volatile("cp.async.commit_group;\n");
    };

    float acc[2][4][4];
#pragma unroll
    for (int mi = 0; mi < 2; mi++)
#pragma unroll
        for (int ni = 0; ni < 4; ni++)
#pragma unroll
            for (int e = 0; e < 4; e++) acc[mi][ni][e] = 0.f;

    const int npro = cpk < 3 ? cpk : 3;
    for (int s = 0; s < npro; s++) issue(cbase + s, s);

    for (int i = 0; i < cpk; i++) {
        const int rem = cpk - 1 - i;
        if (rem >= 2)      asm volatile("cp.async.wait_group 2;\n");
        else if (rem == 1) asm volatile("cp.async.wait_group 1;\n");
        else               asm volatile("cp.async.wait_group 0;\n");
        __syncthreads();
        if (i + 3 < cpk) issue(cbase + i + 3, (i + 3) & 3);

        const float* stg = sm + (i & 3) * STGF_;
        const uint32_t* pA = (const uint32_t*)stg + (wm * 32 + g8) * STRD_ + tg;
        const uint32_t* pB = (const uint32_t*)(stg + STGA_) + (wn * 32 + g8) * STRD_ + tg;
#pragma unroll
        for (int s = 0; s < 4; s++) {
            const int ko = s * 8;
            uint32_t a0[4], a1[4], b[4][2];
            a0[0] = pA[ko];                   a0[1] = pA[8 * STRD_ + ko];
            a0[2] = pA[ko + 4];               a0[3] = pA[8 * STRD_ + ko + 4];
            a1[0] = pA[16 * STRD_ + ko];      a1[1] = pA[24 * STRD_ + ko];
            a1[2] = pA[16 * STRD_ + ko + 4];  a1[3] = pA[24 * STRD_ + ko + 4];
#pragma unroll
            for (int ni = 0; ni < 4; ni++) {
                b[ni][0] = pB[ni * 8 * STRD_ + ko];
                b[ni][1] = pB[ni * 8 * STRD_ + ko + 4];
            }
#pragma unroll
            for (int ni = 0; ni < 4; ni++) {
                mma8(acc[0][ni], a0, b[ni]);
                mma8(acc[1][ni], a1, b[ni]);
            }
        }
    }

    // write this CTA's 64x128 partial
    {
        float* pp = g_part + (size_t)blockIdx.x * 8192;
#pragma unroll
        for (int mi = 0; mi < 2; mi++)
#pragma unroll
            for (int ni = 0; ni < 4; ni++) {
                int r = wm * 32 + mi * 16 + g8, c = wn * 32 + ni * 8 + tg * 2;
                *(float2*)(pp + r * 128 + c)       = make_float2(acc[mi][ni][0], acc[mi][ni][1]);
                *(float2*)(pp + (r + 8) * 128 + c) = make_float2(acc[mi][ni][2], acc[mi][ni][3]);
            }
    }
    __threadfence();
    __syncthreads();

    __shared__ int isLast;
    if (tid == 0) {
        int old = atomicAdd(&g_cnt[grp], 1);
        isLast = (old == SPLIT_ - 1);
    }
    __syncthreads();
    if (!isLast) return;
    if (tid == 0) g_cnt[grp] = 0;
    __threadfence();

    // deterministic reduction of the SPLIT_ partials into smem (64x128)
    float* red = sm;
    for (int e = tid; e < 2048; e += 256) {
        const float* p0 = g_part + (size_t)(grp * SPLIT_) * 8192 + e * 4;
        float4 s = *(const float4*)(p0);
#pragma unroll
        for (int p = 1; p < SPLIT_; p++) {
            float4 v = *(const float4*)(p0 + (size_t)p * 8192);
            s.x += v.x; s.y += v.y; s.z += v.z; s.w += v.w;
        }
        *(float4*)(red + e * 4) = s;
    }
    __syncthreads();

    if (mode == 1) {
        for (int e = tid; e < 2048; e += 256) {
            int m = e >> 5, j = e & 31, n = n0 + j;
            float iv = red[m * 128 + j]      + bi[n]           + bh[n];
            float fv = red[m * 128 + 32 + j] + bi[H_ + n]      + bh[H_ + n];
            float gv = red[m * 128 + 64 + j] + bi[2 * H_ + n]  + bh[2 * H_ + n];
            float ov = red[m * 128 + 96 + j] + bi[3 * H_ + n]  + bh[3 * H_ + n];
            float cp = cprev[(size_t)m * H_ + n];
            float c2 = sigf(fv) * cp + sigf(iv) * tanhf(gv);
            float h2 = sigf(ov) * tanhf(c2);
            cout[(size_t)m * H_ + n] = c2;
            hraw[(size_t)m * H_ + n] = h2;
            hout[(size_t)m * H_ + n] = to_tf32(h2);
        }
    } else if (mode == 0) {
        for (int e = tid; e < 8192; e += 256) {
            int m = e >> 7, c = e & 127;
            float v = tanhf(red[e] + cprev[(size_t)m * H_ + n0 + c]);
            hout[(size_t)m * H_ + n0 + c]   = v;
            g_feed[(size_t)m * H_ + n0 + c] = to_tf32(v);
        }
    } else if (mode == 3) {
        float* outp = (grp < 8) ? hout : hraw;
        for (int e = tid; e < 8192; e += 256) {
            int m = e >> 7, c = e & 127;
            outp[(size_t)m * H_ + nb + c] = red[e];
        }
    } else {
        for (int e = tid; e < 8192; e += 256) {
            int m = e >> 7, c = e & 127;
            hout[(size_t)m * H_ + n0 + c] = red[e];
        }
    }
}

// ---------------- attention scores: grid (8, B), 256 thr; CTA -> 16 s ----------------
__global__ __launch_bounds__(256) void score_kernel(const float* __restrict__ ctx) {
    __shared__ __align__(16) float qs[H_];
    const int b = blockIdx.y, qd = blockIdx.x, tid = threadIdx.x;
    ((float4*)qs)[tid] = ((const float4*)(g_q + (size_t)b * H_))[tid];
    __syncthreads();
    const int w = tid >> 5, l = tid & 31;
    const float4* q4 = (const float4*)qs;
#pragma unroll
    for (int i = 0; i < 2; i++) {
        const int s = qd * 16 + w * 2 + i;
        const float4* row = (const float4*)(ctx + ((size_t)s * B_ + b) * H_);
        float acc = 0.f;
#pragma unroll
        for (int j = 0; j < 8; j++) {
            float4 a = q4[j * 32 + l], c = row[j * 32 + l];
            acc += a.x * c.x + a.y * c.y + a.z * c.z + a.w * c.w;
        }
#pragma unroll
        for (int o = 16; o > 0; o >>= 1) acc += __shfl_xor_sync(0xFFFFFFFFu, acc, o);
        if (!l) g_scores[b * S_ + s] = acc;
    }
}

// ---------------- softmax + cvec: grid (4, B), 256 thr ----------------
__global__ __launch_bounds__(256) void softcvec_kernel(const float* __restrict__ ctx,
                                                       float* __restrict__ attns_t) {
    __shared__ float sc[S_];
    __shared__ float sal[S_];
    __shared__ float red[8];
    const int b = blockIdx.y, qd = blockIdx.x, tid = threadIdx.x;
    const int w = tid >> 5, l = tid & 31;

    if (tid < 128) sc[tid] = g_scores[b * S_ + tid];
    __syncthreads();

    float mx = -3.4e38f;
    if (tid < 128) mx = sc[tid];
#pragma unroll
    for (int o = 16; o > 0; o >>= 1) mx = fmaxf(mx, __shfl_xor_sync(0xFFFFFFFFu, mx, o));
    if (tid < 128 && !l) red[w] = mx;
    __syncthreads();
    const float gmx = fmaxf(fmaxf(red[0], red[1]), fmaxf(red[2], red[3]));
    float e = 0.f;
    if (tid < 128) { e = expf(sc[tid] - gmx); sal[tid] = e; }
    float se = e;
#pragma unroll
    for (int o = 16; o > 0; o >>= 1) se += __shfl_xor_sync(0xFFFFFFFFu, se, o);
    if (tid < 128 && !l) red[4 + w] = se;
    __syncthreads();
    const float inv = 1.f / (red[4] + red[5] + red[6] + red[7]);
    if (tid < 128) {
        float a = sal[tid] * inv;
        sal[tid] = a;
        if (qd == 0) attns_t[(size_t)b * S_ + tid] = a;
    }
    __syncthreads();

    const int d = qd * 256 + tid;
    float acc = 0.f;
#pragma unroll 16
    for (int s = 0; s < S_; s++) acc += sal[s] * ctx[((size_t)s * B_ + b) * H_ + d];
    g_cvec[(size_t)b * H_ + d] = to_tf32(acc);
}

// ---------------- finalize ----------------
__global__ __launch_bounds__(256) void finalize_kernel(float* __restrict__ hF, float* __restrict__ cF) {
    int i = blockIdx.x * blockDim.x + threadIdx.x;
    if (i < BH_) {
        hF[i]       = g_hraw0[i];
        hF[BH_ + i] = g_hraw1[i];
        cF[i]       = g_cb0[i];
        cF[BH_ + i] = g_cb1[i];
    }
}

// ---------------- host launcher ----------------
extern "C" void kernel_launch(void* const* d_in, const int* in_sizes, int n_in,
                              void* d_out, int out_size) {
    const float* inp   = (const float*)d_in[0];
    const float* ctx   = (const float*)d_in[1];
    const float* h0in  = (const float*)d_in[2];
    const float* c0in  = (const float*)d_in[3];
    const float* W_ih0 = (const float*)d_in[4];
    const float* b_ih0 = (const float*)d_in[5];
    const float* W_hh0 = (const float*)d_in[6];
    const float* b_hh0 = (const float*)d_in[7];
    const float* W_ih1 = (const float*)d_in[8];
    const float* b_ih1 = (const float*)d_in[9];
    const float* W_hh1 = (const float*)d_in[10];
    const float* b_hh1 = (const float*)d_in[11];
    const float* W_a   = (const float*)d_in[12];
    const float* W_out = (const float*)d_in[13];

    float* out   = (float*)d_out;
    float* outs  = out;                 // (T,B,H)
    float* hF    = out + TBH_;          // (2,B,H)
    float* cF    = hF + 2 * BH_;        // (2,B,H)
    float* attns = cF + 2 * BH_;        // (T,B,S)

    float *wih0, *whh0, *wih1, *whh1, *wa, *wout_s;
    float *ginp, *hb0, *hb1, *hraw0, *hraw1, *cb0, *cb1, *q, *oh1, *cvec, *feed, *zeros;
    cudaGetSymbolAddress((void**)&wih0, g_wih0);
    cudaGetSymbolAddress((void**)&whh0, g_whh0);
    cudaGetSymbolAddress((void**)&wih1, g_wih1);
    cudaGetSymbolAddress((void**)&whh1, g_whh1);
    cudaGetSymbolAddress((void**)&wa, g_wa);
    cudaGetSymbolAddress((void**)&wout_s, g_wout);
    cudaGetSymbolAddress((void**)&ginp, g_inp);
    cudaGetSymbolAddress((void**)&hb0, g_hb0);
    cudaGetSymbolAddress((void**)&hb1, g_hb1);
    cudaGetSymbolAddress((void**)&hraw0, g_hraw0);
    cudaGetSymbolAddress((void**)&hraw1, g_hraw1);
    cudaGetSymbolAddress((void**)&cb0, g_cb0);
    cudaGetSymbolAddress((void**)&cb1, g_cb1);
    cudaGetSymbolAddress((void**)&q, g_q);
    cudaGetSymbolAddress((void**)&oh1, g_oh1);
    cudaGetSymbolAddress((void**)&cvec, g_cvec);
    cudaGetSymbolAddress((void**)&feed, g_feed);
    cudaGetSymbolAddress((void**)&zeros, g_zeros);

    const int smemB = NSTG_ * STGF_ * sizeof(float);   // 110592
    static int attrSet = 0;
    if (!attrSet) {
        cudaFuncSetAttribute(gemm_kernel, cudaFuncAttributeMaxDynamicSharedMemorySize, smemB);
        attrSet = 1;
    }

    prep_weights<<<2048, 512>>>(W_ih0, W_hh0, W_ih1, W_hh1, W_a, W_out);
    prep_state<<<1024, 512>>>(inp, h0in, c0in);

    for (int t = 0; t < T_; t++) {
        const float* fd  = t ? feed : zeros;
        const float* h0p = hb0 + (size_t)(t & 1) * BH_;
        const float* h1p = hb1 + (size_t)(t & 1) * BH_;
        float* h0n = hb0 + (size_t)((t + 1) & 1) * BH_;
        float* h1n = hb1 + (size_t)((t + 1) & 1) * BH_;

        // layer 0: gates = [emb, feed] @ W_ih0^T + h0 @ W_hh0^T  (32 grp x 8 split)
        gemm_kernel<<<32 * SPLIT_, 256, smemB>>>(
            ginp + (size_t)t * B_ * E_, E_, wih0,       EH_, 16,
            fd,                         H_, wih0 + E_,  EH_, 32,
            h0p,                        H_, whh0,       H_,  32,
            1, b_ih0, b_hh0, cb0, cb0, h0n, hraw0);

        // layer 1
        gemm_kernel<<<32 * SPLIT_, 256, smemB>>>(
            h0n, H_, wih1, H_, 32,
            h1p, H_, whh1, H_, 32,
            h0n, H_, whh1, H_, 0,
            1, b_ih1, b_hh1, cb1, cb1, h1n, hraw1);

        // projh: q = h1 @ Wa^T (grp<8)  AND  oh1 = h1 @ WoutR^T (grp>=8)
        gemm_kernel<<<16 * SPLIT_, 256, smemB>>>(
            h1n, H_, wa,           H_,     32,
            h1n, H_, wout_s + H_,  2 * H_, 0,
            h1n, H_, wa,           H_,     0,
            3, b_ih0, b_hh0, cb0, cb0, q, oh1);

        // attention
        score_kernel<<<dim3(8, B_), 256>>>(ctx);
        softcvec_kernel<<<dim3(4, B_), 256>>>(ctx, attns + (size_t)t * B_ * S_);

        // cvproj: attn_h = tanh(cvec @ WoutL^T + oh1); writes outs[t] + g_feed
        gemm_kernel<<<8 * SPLIT_, 256, smemB>>>(
            cvec, H_, wout_s, 2 * H_, 32,
            cvec, H_, wout_s, 2 * H_, 0,
            cvec, H_, wout_s, 2 * H_, 0,
            0, b_ih0, b_hh0, oh1, cb0, outs + (size_t)t * B_ * H_, hraw0);
    }

    finalize_kernel<<<(BH_ + 255) / 256, 256>>>(hF, cF);
}

// round 9
// speedup vs baseline: 1.1675x; 1.1675x over previous
#include <cuda_runtime.h>
#include <cuda_fp16.h>
#include <math.h>
#include <stdint.h>

#define T_  64
#define B_  64
#define S_  128
#define E_  512
#define H_  1024
#define EH_ 1536
#define BH_ (B_*H_)
#define TBH_ ((size_t)T_*B_*H_)
#define SPLIT_ 8

// ---------------- scratch (device globals; zero-init) ----------------
__device__ __align__(16) __half g_wih0h[(size_t)4*H_*EH_];
__device__ __align__(16) __half g_whh0h[(size_t)4*H_*H_];
__device__ __align__(16) __half g_wih1h[(size_t)4*H_*H_];
__device__ __align__(16) __half g_whh1h[(size_t)4*H_*H_];
__device__ __align__(16) __half g_wah[(size_t)H_*H_];
__device__ __align__(16) __half g_wouth[(size_t)H_*2*H_];
__device__ __align__(16) __half g_inph[(size_t)T_*B_*E_];
__device__ __align__(16) __half g_ctxh[(size_t)S_*B_*H_];
__device__ __align__(16) __half g_hb0h[2*BH_];   // layer0 h ping-pong (half)
__device__ __align__(16) __half g_hb1h[2*BH_];
__device__ __align__(16) __half g_cvech[BH_];
__device__ __align__(16) __half g_feedh[BH_];
__device__ __align__(16) __half g_zerosh[BH_];   // never written -> 0
__device__ __align__(16) float g_hraw0[BH_];     // fp32 h for hF
__device__ __align__(16) float g_hraw1[BH_];
__device__ __align__(16) float g_cb0[BH_];
__device__ __align__(16) float g_cb1[BH_];
__device__ __align__(16) float g_q[BH_];         // h1 @ Wa^T (fp32)
__device__ __align__(16) float g_oh1[BH_];       // h1 @ WoutR^T (fp32)
__device__ __align__(16) float g_scores[B_*S_];
__device__ __align__(16) float g_part[(size_t)256*8192];  // split-K partials
__device__ int g_cnt[64];

__device__ __forceinline__ float sigf(float x) { return 1.f / (1.f + expf(-x)); }

__device__ __forceinline__ void cp16(void* dst, const void* src) {
    unsigned s = (unsigned)__cvta_generic_to_shared(dst);
    asm volatile("cp.async.cg.shared.global [%0], [%1], 16;\n" :: "r"(s), "l"(src));
}

__device__ __forceinline__ void mma16(float* c, const uint32_t* a, const uint32_t* b) {
    asm volatile(
        "mma.sync.aligned.m16n8k16.row.col.f32.f16.f16.f32 "
        "{%0,%1,%2,%3}, {%4,%5,%6,%7}, {%8,%9}, {%0,%1,%2,%3};\n"
        : "+f"(c[0]), "+f"(c[1]), "+f"(c[2]), "+f"(c[3])
        : "r"(a[0]), "r"(a[1]), "r"(a[2]), "r"(a[3]), "r"(b[0]), "r"(b[1]));
}

// ---------------- prep: convert weights to fp16 ----------------
__global__ __launch_bounds__(512) void prep_weights(
    const float* __restrict__ wih0, const float* __restrict__ whh0,
    const float* __restrict__ wih1, const float* __restrict__ whh1,
    const float* __restrict__ wa,   const float* __restrict__ wout) {
    const size_t n0 = (size_t)4 * H_ * EH_;
    const size_t n1 = (size_t)4 * H_ * H_;
    const size_t n2 = (size_t)H_ * H_;
    const size_t n3 = (size_t)H_ * 2 * H_;
    const size_t tot = n0 + 3 * n1 + n2 + n3;
    for (size_t i = (size_t)blockIdx.x * blockDim.x + threadIdx.x; i < tot;
         i += (size_t)gridDim.x * blockDim.x) {
        size_t j = i; float v; __half* d;
        if (j < n0) { v = wih0[j]; d = g_wih0h + j; }
        else { j -= n0;
        if (j < n1) { v = whh0[j]; d = g_whh0h + j; }
        else { j -= n1;
        if (j < n1) { v = wih1[j]; d = g_wih1h + j; }
        else { j -= n1;
        if (j < n1) { v = whh1[j]; d = g_whh1h + j; }
        else { j -= n1;
        if (j < n2) { v = wa[j];   d = g_wah + j; }
        else { j -= n2; v = wout[j]; d = g_wouth + j; } } } } }
        *d = __float2half_rn(v);
    }
}

// ---------------- prep: inp/ctx to half, init states ----------------
__global__ __launch_bounds__(512) void prep_state(const float* __restrict__ inp,
                                                  const float* __restrict__ ctx,
                                                  const float* __restrict__ h0,
                                                  const float* __restrict__ c0) {
    const size_t ninp = (size_t)T_ * B_ * E_;
    const size_t nctx = (size_t)S_ * B_ * H_;
    const size_t tot = ninp + nctx + 2 * BH_;
    for (size_t i = (size_t)blockIdx.x * blockDim.x + threadIdx.x; i < tot;
         i += (size_t)gridDim.x * blockDim.x) {
        if (i < ninp) { g_inph[i] = __float2half_rn(inp[i]); continue; }
        size_t j = i - ninp;
        if (j < nctx) { g_ctxh[j] = __float2half_rn(ctx[j]); continue; }
        j -= nctx;
        if (j < BH_) { g_hb0h[j] = __float2half_rn(h0[j]); g_cb0[j] = c0[j]; }
        else { j -= BH_; g_hb1h[j] = __float2half_rn(h0[BH_ + j]); g_cb1[j] = c0[BH_ + j]; }
    }
}

// ---------------- fp16 split-K GEMM, tile 64x128, last-CTA epilogue ----------------
// C(64 x 128 cols) = sum_seg A_seg(64,K) @ W_seg(cols,K)^T, fp16 mma, fp32 acc.
// 256 threads, 8 warps 2(m) x 4(n), warp tile 32x32, K-chunk 32 halves.
// mode 1: cols {gate*H + n0 + j}, n0=grp*32; LSTM cell epilogue.
// mode 0: cols n0..n0+127; C += cprev(oh1); tanh -> houtf + half -> houth.
// mode 3: grp<8 -> houtf (q), grp>=8 -> hraw (oh1); plain fp32 stores.
#define STRDH 40                 // halves per smem row (32 + 8 pad)
#define STGA_H (64*STRDH)        // 2560 halves
#define STGF_H (192*STRDH)       // stage total: 7680 halves (15360 B)
#define NSTG_ 4
__global__ __launch_bounds__(256) void gemm_kernel(
    const __half* __restrict__ A0, int lda0, const __half* __restrict__ W0, int ldw0, int kt0,
    const __half* __restrict__ A1, int lda1, const __half* __restrict__ W1, int ldw1, int kt1,
    const __half* __restrict__ A2, int lda2, const __half* __restrict__ W2, int ldw2, int kt2,
    int mode,
    const float* __restrict__ bi, const float* __restrict__ bh,
    const float* __restrict__ cprev, float* __restrict__ cout,
    float* __restrict__ houtf, __half* __restrict__ houth, float* __restrict__ hraw) {

    extern __shared__ __align__(16) __half smh[];   // NSTG_ * STGF_H halves

    const int tid = threadIdx.x;
    const int w = tid >> 5, lane = tid & 31;
    const int wm = w >> 2, wn = w & 3;              // 2 x 4 warp grid
    const int g8 = lane >> 2, tg = lane & 3;
    const int grp = blockIdx.x / SPLIT_;
    const int sk  = blockIdx.x % SPLIT_;
    const int n0  = grp * (mode == 1 ? 32 : 128);

    const __half* Wsel = W0; int lwsel = ldw0; int nb = n0;
    if (mode == 3 && grp >= 8) { Wsel = W1; lwsel = ldw1; nb = n0 - 1024; }

    const int tot = kt0 + kt1 + kt2;
    const int cpk = tot / SPLIT_;
    const int cbase = sk * cpk;

    // copy map: A 256 chunks (1/thread), W 512 chunks (2/thread); 16B = 8 halves each
    const int rA = tid >> 2, cA = (tid & 3) * 8;
    int rW[2], cW[2], wrW[2];
#pragma unroll
    for (int j = 0; j < 2; j++) {
        int qk = j * 256 + tid;
        rW[j] = qk >> 2; cW[j] = (qk & 3) * 8;
        wrW[j] = (mode == 1) ? ((rW[j] >> 5) * H_ + n0 + (rW[j] & 31)) : (nb + rW[j]);
    }

    auto issue = [&](int c, int buf) {
        const __half* Ab; const __half* Wb; int la, lw, ko;
        if (c < kt0)            { Ab = A0; Wb = W0; la = lda0; lw = ldw0; ko = c * 32; }
        else if (c < kt0 + kt1) { Ab = A1; Wb = W1; la = lda1; lw = ldw1; ko = (c - kt0) * 32; }
        else                    { Ab = A2; Wb = W2; la = lda2; lw = ldw2; ko = (c - kt0 - kt1) * 32; }
        if (mode == 3) { Wb = Wsel; lw = lwsel; }
        __half* st = smh + buf * STGF_H;
        cp16(st + rA * STRDH + cA, Ab + (size_t)rA * la + ko + cA);
#pragma unroll
        for (int j = 0; j < 2; j++)
            cp16(st + STGA_H + rW[j] * STRDH + cW[j], Wb + (size_t)wrW[j] * lw + ko + cW[j]);
        asm volatile("cp.async.commit_group;\n");
    };

    float acc[2][4][4];
#pragma unroll
    for (int mi = 0; mi < 2; mi++)
#pragma unroll
        for (int ni = 0; ni < 4; ni++)
#pragma unroll
            for (int e = 0; e < 4; e++) acc[mi][ni][e] = 0.f;

    const int npro = cpk < 3 ? cpk : 3;
    for (int s = 0; s < npro; s++) issue(cbase + s, s);

    for (int i = 0; i < cpk; i++) {
        const int rem = cpk - 1 - i;
        if (rem >= 2)      asm volatile("cp.async.wait_group 2;\n");
        else if (rem == 1) asm volatile("cp.async.wait_group 1;\n");
        else               asm volatile("cp.async.wait_group 0;\n");
        __syncthreads();
        if (i + 3 < cpk) issue(cbase + i + 3, (i + 3) & 3);

        const __half* stg = smh + (i & 3) * STGF_H;
        // b32 view: row stride = STRDH/2 = 20
        const uint32_t* pA = (const uint32_t*)stg + (wm * 32 + g8) * 20 + tg;
        const uint32_t* pB = (const uint32_t*)(stg + STGA_H) + (wn * 32 + g8) * 20 + tg;
#pragma unroll
        for (int kk = 0; kk < 2; kk++) {           // two k16 steps per 32-chunk
            const int ko = kk * 8;                  // b32 offset of k16 step
            uint32_t a0[4], a1[4], b[4][2];
            a0[0] = pA[ko];            a0[1] = pA[8 * 20 + ko];
            a0[2] = pA[ko + 4];        a0[3] = pA[8 * 20 + ko + 4];
            a1[0] = pA[16 * 20 + ko];  a1[1] = pA[24 * 20 + ko];
            a1[2] = pA[16 * 20 + ko + 4]; a1[3] = pA[24 * 20 + ko + 4];
#pragma unroll
            for (int ni = 0; ni < 4; ni++) {
                b[ni][0] = pB[ni * 8 * 20 + ko];
                b[ni][1] = pB[ni * 8 * 20 + ko + 4];
            }
#pragma unroll
            for (int ni = 0; ni < 4; ni++) {
                mma16(acc[0][ni], a0, b[ni]);
                mma16(acc[1][ni], a1, b[ni]);
            }
        }
    }

    // write 64x128 partial
    {
        float* pp = g_part + (size_t)blockIdx.x * 8192;
#pragma unroll
        for (int mi = 0; mi < 2; mi++)
#pragma unroll
            for (int ni = 0; ni < 4; ni++) {
                int r = wm * 32 + mi * 16 + g8, c = wn * 32 + ni * 8 + tg * 2;
                *(float2*)(pp + r * 128 + c)       = make_float2(acc[mi][ni][0], acc[mi][ni][1]);
                *(float2*)(pp + (r + 8) * 128 + c) = make_float2(acc[mi][ni][2], acc[mi][ni][3]);
            }
    }
    __threadfence();
    __syncthreads();

    __shared__ int isLast;
    if (tid == 0) {
        int old = atomicAdd(&g_cnt[grp], 1);
        isLast = (old == SPLIT_ - 1);
    }
    __syncthreads();
    if (!isLast) return;
    if (tid == 0) g_cnt[grp] = 0;
    __threadfence();

    // deterministic fixed-order reduction into smem (64x128 fp32)
    float* red = (float*)smh;
    for (int e = tid; e < 2048; e += 256) {
        const float* p0 = g_part + (size_t)(grp * SPLIT_) * 8192 + e * 4;
        float4 s = *(const float4*)(p0);
#pragma unroll
        for (int p = 1; p < SPLIT_; p++) {
            float4 v = *(const float4*)(p0 + (size_t)p * 8192);
            s.x += v.x; s.y += v.y; s.z += v.z; s.w += v.w;
        }
        *(float4*)(red + e * 4) = s;
    }
    __syncthreads();

    if (mode == 1) {
        for (int e = tid; e < 2048; e += 256) {
            int m = e >> 5, j = e & 31, n = n0 + j;
            float iv = red[m * 128 + j]      + bi[n]           + bh[n];
            float fv = red[m * 128 + 32 + j] + bi[H_ + n]      + bh[H_ + n];
            float gv = red[m * 128 + 64 + j] + bi[2 * H_ + n]  + bh[2 * H_ + n];
            float ov = red[m * 128 + 96 + j] + bi[3 * H_ + n]  + bh[3 * H_ + n];
            float cp = cprev[(size_t)m * H_ + n];
            float c2 = sigf(fv) * cp + sigf(iv) * tanhf(gv);
            float h2 = sigf(ov) * tanhf(c2);
            cout[(size_t)m * H_ + n]  = c2;
            hraw[(size_t)m * H_ + n]  = h2;
            houth[(size_t)m * H_ + n] = __float2half_rn(h2);
        }
    } else if (mode == 0) {
        for (int e = tid; e < 8192; e += 256) {
            int m = e >> 7, c = e & 127;
            float v = tanhf(red[e] + cprev[(size_t)m * H_ + n0 + c]);
            houtf[(size_t)m * H_ + n0 + c] = v;
            houth[(size_t)m * H_ + n0 + c] = __float2half_rn(v);
        }
    } else {   // mode 3
        float* outp = (grp < 8) ? houtf : hraw;
        for (int e = tid; e < 8192; e += 256) {
            int m = e >> 7, c = e & 127;
            outp[(size_t)m * H_ + nb + c] = red[e];
        }
    }
}

// ---------------- attention scores (half ctx): grid (8, B), 256 thr ----------------
__global__ __launch_bounds__(256) void score_kernel() {
    __shared__ __align__(16) float qs[H_];
    const int b = blockIdx.y, qd = blockIdx.x, tid = threadIdx.x;
    ((float4*)qs)[tid] = ((const float4*)(g_q + (size_t)b * H_))[tid];
    __syncthreads();
    const int w = tid >> 5, l = tid & 31;
#pragma unroll
    for (int i = 0; i < 2; i++) {
        const int s = qd * 16 + w * 2 + i;
        const uint4* row = (const uint4*)(g_ctxh + ((size_t)s * B_ + b) * H_);  // 8 halves/uint4
        float acc = 0.f;
#pragma unroll
        for (int j = 0; j < 4; j++) {
            uint4 cv = row[j * 32 + l];
            const float* qp = qs + j * 256 + l * 8;
            float2 c0 = __half22float2(*(const __half2*)&cv.x);
            float2 c1 = __half22float2(*(const __half2*)&cv.y);
            float2 c2 = __half22float2(*(const __half2*)&cv.z);
            float2 c3 = __half22float2(*(const __half2*)&cv.w);
            acc += qp[0] * c0.x + qp[1] * c0.y + qp[2] * c1.x + qp[3] * c1.y
                 + qp[4] * c2.x + qp[5] * c2.y + qp[6] * c3.x + qp[7] * c3.y;
        }
#pragma unroll
        for (int o = 16; o > 0; o >>= 1) acc += __shfl_xor_sync(0xFFFFFFFFu, acc, o);
        if (!l) g_scores[b * S_ + s] = acc;
    }
}

// ---------------- softmax + cvec (fp32 ctx): grid (4, B), 256 thr ----------------
__global__ __launch_bounds__(256) void softcvec_kernel(const float* __restrict__ ctx,
                                                       float* __restrict__ attns_t) {
    __shared__ float sc[S_];
    __shared__ float sal[S_];
    __shared__ float red[8];
    const int b = blockIdx.y, qd = blockIdx.x, tid = threadIdx.x;
    const int w = tid >> 5, l = tid & 31;

    if (tid < 128) sc[tid] = g_scores[b * S_ + tid];
    __syncthreads();

    float mx = -3.4e38f;
    if (tid < 128) mx = sc[tid];
#pragma unroll
    for (int o = 16; o > 0; o >>= 1) mx = fmaxf(mx, __shfl_xor_sync(0xFFFFFFFFu, mx, o));
    if (tid < 128 && !l) red[w] = mx;
    __syncthreads();
    const float gmx = fmaxf(fmaxf(red[0], red[1]), fmaxf(red[2], red[3]));
    float e = 0.f;
    if (tid < 128) { e = expf(sc[tid] - gmx); sal[tid] = e; }
    float se = e;
#pragma unroll
    for (int o = 16; o > 0; o >>= 1) se += __shfl_xor_sync(0xFFFFFFFFu, se, o);
    if (tid < 128 && !l) red[4 + w] = se;
    __syncthreads();
    const float inv = 1.f / (red[4] + red[5] + red[6] + red[7]);
    if (tid < 128) {
        float a = sal[tid] * inv;
        sal[tid] = a;
        if (qd == 0) attns_t[(size_t)b * S_ + tid] = a;
    }
    __syncthreads();

    const int d = qd * 256 + tid;
    float acc = 0.f;
#pragma unroll 16
    for (int s = 0; s < S_; s++) acc += sal[s] * ctx[((size_t)s * B_ + b) * H_ + d];
    g_cvech[(size_t)b * H_ + d] = __float2half_rn(acc);
}

// ---------------- finalize ----------------
__global__ __launch_bounds__(256) void finalize_kernel(float* __restrict__ hF, float* __restrict__ cF) {
    int i = blockIdx.x * blockDim.x + threadIdx.x;
    if (i < BH_) {
        hF[i]       = g_hraw0[i];
        hF[BH_ + i] = g_hraw1[i];
        cF[i]       = g_cb0[i];
        cF[BH_ + i] = g_cb1[i];
    }
}

// ---------------- host launcher ----------------
extern "C" void kernel_launch(void* const* d_in, const int* in_sizes, int n_in,
                              void* d_out, int out_size) {
    const float* inp   = (const float*)d_in[0];
    const float* ctx   = (const float*)d_in[1];
    const float* h0in  = (const float*)d_in[2];
    const float* c0in  = (const float*)d_in[3];
    const float* W_ih0 = (const float*)d_in[4];
    const float* b_ih0 = (const float*)d_in[5];
    const float* W_hh0 = (const float*)d_in[6];
    const float* b_hh0 = (const float*)d_in[7];
    const float* W_ih1 = (const float*)d_in[8];
    const float* b_ih1 = (const float*)d_in[9];
    const float* W_hh1 = (const float*)d_in[10];
    const float* b_hh1 = (const float*)d_in[11];
    const float* W_a   = (const float*)d_in[12];
    const float* W_out = (const float*)d_in[13];

    float* out   = (float*)d_out;
    float* outs  = out;                 // (T,B,H)
    float* hF    = out + TBH_;          // (2,B,H)
    float* cF    = hF + 2 * BH_;        // (2,B,H)
    float* attns = cF + 2 * BH_;        // (T,B,S)

    __half *wih0h, *whh0h, *wih1h, *whh1h, *wah, *wouth;
    __half *inph, *hb0h, *hb1h, *cvech, *feedh, *zerosh;
    float *hraw0, *hraw1, *cb0, *cb1, *q, *oh1;
    cudaGetSymbolAddress((void**)&wih0h, g_wih0h);
    cudaGetSymbolAddress((void**)&whh0h, g_whh0h);
    cudaGetSymbolAddress((void**)&wih1h, g_wih1h);
    cudaGetSymbolAddress((void**)&whh1h, g_whh1h);
    cudaGetSymbolAddress((void**)&wah, g_wah);
    cudaGetSymbolAddress((void**)&wouth, g_wouth);
    cudaGetSymbolAddress((void**)&inph, g_inph);
    cudaGetSymbolAddress((void**)&hb0h, g_hb0h);
    cudaGetSymbolAddress((void**)&hb1h, g_hb1h);
    cudaGetSymbolAddress((void**)&cvech, g_cvech);
    cudaGetSymbolAddress((void**)&feedh, g_feedh);
    cudaGetSymbolAddress((void**)&zerosh, g_zerosh);
    cudaGetSymbolAddress((void**)&hraw0, g_hraw0);
    cudaGetSymbolAddress((void**)&hraw1, g_hraw1);
    cudaGetSymbolAddress((void**)&cb0, g_cb0);
    cudaGetSymbolAddress((void**)&cb1, g_cb1);
    cudaGetSymbolAddress((void**)&q, g_q);
    cudaGetSymbolAddress((void**)&oh1, g_oh1);

    const int smemB = NSTG_ * STGF_H * sizeof(__half);   // 61440
    static int attrSet = 0;
    if (!attrSet) {
        cudaFuncSetAttribute(gemm_kernel, cudaFuncAttributeMaxDynamicSharedMemorySize, smemB);
        attrSet = 1;
    }

    prep_weights<<<2048, 512>>>(W_ih0, W_hh0, W_ih1, W_hh1, W_a, W_out);
    prep_state<<<2048, 512>>>(inp, ctx, h0in, c0in);

    for (int t = 0; t < T_; t++) {
        const __half* fd  = t ? feedh : zerosh;
        const __half* h0p = hb0h + (size_t)(t & 1) * BH_;
        const __half* h1p = hb1h + (size_t)(t & 1) * BH_;
        __half* h0n = hb0h + (size_t)((t + 1) & 1) * BH_;
        __half* h1n = hb1h + (size_t)((t + 1) & 1) * BH_;

        // layer 0: gates = [emb, feed] @ W_ih0^T + h0 @ W_hh0^T  (32 grp x 8 split)
        gemm_kernel<<<32 * SPLIT_, 256, smemB>>>(
            inph + (size_t)t * B_ * E_, E_, wih0h,       EH_, 16,
            fd,                         H_, wih0h + E_,  EH_, 32,
            h0p,                        H_, whh0h,       H_,  32,
            1, b_ih0, b_hh0, cb0, cb0, nullptr, h0n, hraw0);

        // layer 1
        gemm_kernel<<<32 * SPLIT_, 256, smemB>>>(
            h0n, H_, wih1h, H_, 32,
            h1p, H_, whh1h, H_, 32,
            h0n, H_, whh1h, H_, 0,
            1, b_ih1, b_hh1, cb1, cb1, nullptr, h1n, hraw1);

        // projh: q = h1 @ Wa^T (grp<8) AND oh1 = h1 @ WoutR^T (grp>=8)
        gemm_kernel<<<16 * SPLIT_, 256, smemB>>>(
            h1n, H_, wah,          H_,     32,
            h1n, H_, wouth + H_,   2 * H_, 0,
            h1n, H_, wah,          H_,     0,
            3, b_ih0, b_hh0, cb0, cb0, q, nullptr, oh1);

        // attention
        score_kernel<<<dim3(8, B_), 256>>>();
        softcvec_kernel<<<dim3(4, B_), 256>>>(ctx, attns + (size_t)t * B_ * S_);

        // cvproj: attn_h = tanh(cvec @ WoutL^T + oh1) -> outs[t] fp32 + feed half
        gemm_kernel<<<8 * SPLIT_, 256, smemB>>>(
            cvech, H_, wouth, 2 * H_, 32,
            cvech, H_, wouth, 2 * H_, 0,
            cvech, H_, wouth, 2 * H_, 0,
            0, b_ih0, b_hh0, oh1, cb0, outs + (size_t)t * B_ * H_, feedh, nullptr);
    }

    finalize_kernel<<<(BH_ + 255) / 256, 256>>>(hF, cF);
}

// round 10
// speedup vs baseline: 1.6700x; 1.4304x over previous
#include <cuda_runtime.h>
#include <cuda_fp16.h>
#include <math.h>
#include <stdint.h>

#define T_  64
#define B_  64
#define S_  128
#define E_  512
#define H_  1024
#define EH_ 1536
#define BH_ (B_*H_)
#define TBH_ ((size_t)T_*B_*H_)

// ---------------- scratch (device globals; zero-init) ----------------
__device__ __align__(16) __half g_wih0h[(size_t)4*H_*EH_];
__device__ __align__(16) __half g_whh0h[(size_t)4*H_*H_];
__device__ __align__(16) __half g_wih1h[(size_t)4*H_*H_];
__device__ __align__(16) __half g_whh1h[(size_t)4*H_*H_];
__device__ __align__(16) __half g_wah[(size_t)H_*H_];
__device__ __align__(16) __half g_wouth[(size_t)H_*2*H_];
__device__ __align__(16) __half g_inph[(size_t)T_*B_*E_];
__device__ __align__(16) __half g_ctxh[(size_t)S_*B_*H_];
__device__ __align__(16) __half g_hb0h[2*BH_];   // layer0 h ping-pong (half)
__device__ __align__(16) __half g_hb1h[2*BH_];
__device__ __align__(16) __half g_cvech[BH_];
__device__ __align__(16) __half g_feedh[BH_];
__device__ __align__(16) __half g_zerosh[BH_];   // never written -> 0
__device__ __align__(16) float g_hraw0[BH_];     // fp32 h for hF
__device__ __align__(16) float g_hraw1[BH_];
__device__ __align__(16) float g_cb0[BH_];
__device__ __align__(16) float g_cb1[BH_];
__device__ __align__(16) float g_q[BH_];         // h1 @ Wa^T (fp32)
__device__ __align__(16) float g_oh1[BH_];       // h1 @ WoutR^T (fp32)
__device__ __align__(16) float g_part[(size_t)256*8192];  // split-K partials
__device__ int g_cnt[64];
__device__ int g_done[64];

__device__ __forceinline__ float sigf(float x) { return 1.f / (1.f + expf(-x)); }

__device__ __forceinline__ void cp16(void* dst, const void* src) {
    unsigned s = (unsigned)__cvta_generic_to_shared(dst);
    asm volatile("cp.async.cg.shared.global [%0], [%1], 16;\n" :: "r"(s), "l"(src));
}

__device__ __forceinline__ void mma16(float* c, const uint32_t* a, const uint32_t* b) {
    asm volatile(
        "mma.sync.aligned.m16n8k16.row.col.f32.f16.f16.f32 "
        "{%0,%1,%2,%3}, {%4,%5,%6,%7}, {%8,%9}, {%0,%1,%2,%3};\n"
        : "+f"(c[0]), "+f"(c[1]), "+f"(c[2]), "+f"(c[3])
        : "r"(a[0]), "r"(a[1]), "r"(a[2]), "r"(a[3]), "r"(b[0]), "r"(b[1]));
}

// ---------------- prep: convert weights to fp16 ----------------
__global__ __launch_bounds__(512) void prep_weights(
    const float* __restrict__ wih0, const float* __restrict__ whh0,
    const float* __restrict__ wih1, const float* __restrict__ whh1,
    const float* __restrict__ wa,   const float* __restrict__ wout) {
    const size_t n0 = (size_t)4 * H_ * EH_;
    const size_t n1 = (size_t)4 * H_ * H_;
    const size_t n2 = (size_t)H_ * H_;
    const size_t n3 = (size_t)H_ * 2 * H_;
    const size_t tot = n0 + 3 * n1 + n2 + n3;
    for (size_t i = (size_t)blockIdx.x * blockDim.x + threadIdx.x; i < tot;
         i += (size_t)gridDim.x * blockDim.x) {
        size_t j = i; float v; __half* d;
        if (j < n0) { v = wih0[j]; d = g_wih0h + j; }
        else { j -= n0;
        if (j < n1) { v = whh0[j]; d = g_whh0h + j; }
        else { j -= n1;
        if (j < n1) { v = wih1[j]; d = g_wih1h + j; }
        else { j -= n1;
        if (j < n1) { v = whh1[j]; d = g_whh1h + j; }
        else { j -= n1;
        if (j < n2) { v = wa[j];   d = g_wah + j; }
        else { j -= n2; v = wout[j]; d = g_wouth + j; } } } } }
        *d = __float2half_rn(v);
    }
}

// ---------------- prep: inp/ctx to half, init states ----------------
__global__ __launch_bounds__(512) void prep_state(const float* __restrict__ inp,
                                                  const float* __restrict__ ctx,
                                                  const float* __restrict__ h0,
                                                  const float* __restrict__ c0) {
    const size_t ninp = (size_t)T_ * B_ * E_;
    const size_t nctx = (size_t)S_ * B_ * H_;
    const size_t tot = ninp + nctx + 2 * BH_;
    for (size_t i = (size_t)blockIdx.x * blockDim.x + threadIdx.x; i < tot;
         i += (size_t)gridDim.x * blockDim.x) {
        if (i < ninp) { g_inph[i] = __float2half_rn(inp[i]); continue; }
        size_t j = i - ninp;
        if (j < nctx) { g_ctxh[j] = __float2half_rn(ctx[j]); continue; }
        j -= nctx;
        if (j < BH_) { g_hb0h[j] = __float2half_rn(h0[j]); g_cb0[j] = c0[j]; }
        else { j -= BH_; g_hb1h[j] = __float2half_rn(h0[BH_ + j]); g_cb1[j] = c0[BH_ + j]; }
    }
}

// ---------------- fp16 split-K GEMM, tile 64x128, DISTRIBUTED epilogue ----------------
// C(64 x 128 cols) = sum_seg A_seg(64,K) @ W_seg(cols,K)^T, fp16 mma, fp32 acc.
// grid = NGRP * split. All split CTAs write partials, barrier on g_cnt, then each
// CTA reduces+epilogues its own (64/split)-row slice. Deterministic fixed-order sums.
// mode 1: cols {gate*H + n0 + j}, n0=grp*32; LSTM cell epilogue.
// mode 0: cols n0..n0+127; C += cprev(oh1); tanh -> houtf + half -> houth.
// mode 3: grp<8 -> houtf (q), grp>=8 -> hraw (oh1); plain fp32 stores.
#define STRDH 40                 // halves per smem row (32 + 8 pad)
#define STGA_H (64*STRDH)        // 2560 halves
#define STGF_H (192*STRDH)       // stage total: 7680 halves (15360 B)
#define NSTG_ 4
__global__ __launch_bounds__(256) void gemm_kernel(
    const __half* __restrict__ A0, int lda0, const __half* __restrict__ W0, int ldw0, int kt0,
    const __half* __restrict__ A1, int lda1, const __half* __restrict__ W1, int ldw1, int kt1,
    const __half* __restrict__ A2, int lda2, const __half* __restrict__ W2, int ldw2, int kt2,
    int mode, int split,
    const float* __restrict__ bi, const float* __restrict__ bh,
    const float* __restrict__ cprev, float* __restrict__ cout,
    float* __restrict__ houtf, __half* __restrict__ houth, float* __restrict__ hraw) {

    extern __shared__ __align__(16) __half smh[];   // NSTG_ * STGF_H halves

    const int tid = threadIdx.x;
    const int w = tid >> 5, lane = tid & 31;
    const int wm = w >> 2, wn = w & 3;              // 2 x 4 warp grid
    const int g8 = lane >> 2, tg = lane & 3;
    const int grp = blockIdx.x / split;
    const int sk  = blockIdx.x % split;
    const int n0  = grp * (mode == 1 ? 32 : 128);

    const __half* Wsel = W0; int lwsel = ldw0; int nb = n0;
    if (mode == 3 && grp >= 8) { Wsel = W1; lwsel = ldw1; nb = n0 - 1024; }

    const int tot = kt0 + kt1 + kt2;
    const int cpk = tot / split;
    const int cbase = sk * cpk;

    // copy map: A 256 chunks (1/thread), W 512 chunks (2/thread); 16B = 8 halves each
    const int rA = tid >> 2, cA = (tid & 3) * 8;
    int rW[2], cW[2], wrW[2];
#pragma unroll
    for (int j = 0; j < 2; j++) {
        int qk = j * 256 + tid;
        rW[j] = qk >> 2; cW[j] = (qk & 3) * 8;
        wrW[j] = (mode == 1) ? ((rW[j] >> 5) * H_ + n0 + (rW[j] & 31)) : (nb + rW[j]);
    }

    auto issue = [&](int c, int buf) {
        const __half* Ab; const __half* Wb; int la, lw, ko;
        if (c < kt0)            { Ab = A0; Wb = W0; la = lda0; lw = ldw0; ko = c * 32; }
        else if (c < kt0 + kt1) { Ab = A1; Wb = W1; la = lda1; lw = ldw1; ko = (c - kt0) * 32; }
        else                    { Ab = A2; Wb = W2; la = lda2; lw = ldw2; ko = (c - kt0 - kt1) * 32; }
        if (mode == 3) { Wb = Wsel; lw = lwsel; }
        __half* st = smh + buf * STGF_H;
        cp16(st + rA * STRDH + cA, Ab + (size_t)rA * la + ko + cA);
#pragma unroll
        for (int j = 0; j < 2; j++)
            cp16(st + STGA_H + rW[j] * STRDH + cW[j], Wb + (size_t)wrW[j] * lw + ko + cW[j]);
        asm volatile("cp.async.commit_group;\n");
    };

    float acc[2][4][4];
#pragma unroll
    for (int mi = 0; mi < 2; mi++)
#pragma unroll
        for (int ni = 0; ni < 4; ni++)
#pragma unroll
            for (int e = 0; e < 4; e++) acc[mi][ni][e] = 0.f;

    const int npro = cpk < 3 ? cpk : 3;
    for (int s = 0; s < npro; s++) issue(cbase + s, s);

    for (int i = 0; i < cpk; i++) {
        const int rem = cpk - 1 - i;
        if (rem >= 2)      asm volatile("cp.async.wait_group 2;\n");
        else if (rem == 1) asm volatile("cp.async.wait_group 1;\n");
        else               asm volatile("cp.async.wait_group 0;\n");
        __syncthreads();
        if (i + 3 < cpk) issue(cbase + i + 3, (i + 3) & 3);

        const __half* stg = smh + (i & 3) * STGF_H;
        const uint32_t* pA = (const uint32_t*)stg + (wm * 32 + g8) * 20 + tg;
        const uint32_t* pB = (const uint32_t*)(stg + STGA_H) + (wn * 32 + g8) * 20 + tg;
#pragma unroll
        for (int kk = 0; kk < 2; kk++) {
            const int ko = kk * 8;
            uint32_t a0[4], a1[4], b[4][2];
            a0[0] = pA[ko];            a0[1] = pA[8 * 20 + ko];
            a0[2] = pA[ko + 4];        a0[3] = pA[8 * 20 + ko + 4];
            a1[0] = pA[16 * 20 + ko];  a1[1] = pA[24 * 20 + ko];
            a1[2] = pA[16 * 20 + ko + 4]; a1[3] = pA[24 * 20 + ko + 4];
#pragma unroll
            for (int ni = 0; ni < 4; ni++) {
                b[ni][0] = pB[ni * 8 * 20 + ko];
                b[ni][1] = pB[ni * 8 * 20 + ko + 4];
            }
#pragma unroll
            for (int ni = 0; ni < 4; ni++) {
                mma16(acc[0][ni], a0, b[ni]);
                mma16(acc[1][ni], a1, b[ni]);
            }
        }
    }

    // write 64x128 partial
    {
        float* pp = g_part + (size_t)blockIdx.x * 8192;
#pragma unroll
        for (int mi = 0; mi < 2; mi++)
#pragma unroll
            for (int ni = 0; ni < 4; ni++) {
                int r = wm * 32 + mi * 16 + g8, c = wn * 32 + ni * 8 + tg * 2;
                *(float2*)(pp + r * 128 + c)       = make_float2(acc[mi][ni][0], acc[mi][ni][1]);
                *(float2*)(pp + (r + 8) * 128 + c) = make_float2(acc[mi][ni][2], acc[mi][ni][3]);
            }
    }
    __threadfence();
    __syncthreads();

    // arrive + wait for all split partials of this group
    if (tid == 0) {
        atomicAdd(&g_cnt[grp], 1);
        unsigned v;
        do {
            asm volatile("ld.acquire.gpu.u32 %0, [%1];" : "=r"(v) : "l"(&g_cnt[grp]));
        } while ((int)v < split);
    }
    __syncthreads();
    __threadfence();

    // each CTA reduces + epilogues its own row slice (deterministic order)
    const int rpc = 64 / split;              // rows per CTA
    const int base = sk * rpc * 128;
    float* red = (float*)smh;                // rpc*128 floats
    for (int e4 = tid; e4 < rpc * 32; e4 += 256) {
        const float* p0 = g_part + (size_t)(grp * split) * 8192 + base + e4 * 4;
        float4 s = *(const float4*)(p0);
        for (int p = 1; p < split; p++) {
            float4 v = *(const float4*)(p0 + (size_t)p * 8192);
            s.x += v.x; s.y += v.y; s.z += v.z; s.w += v.w;
        }
        *(float4*)(red + e4 * 4) = s;
    }
    __syncthreads();

    if (mode == 1) {
        for (int e = tid; e < rpc * 32; e += 256) {
            int lm = e >> 5, j = e & 31;
            int m = sk * rpc + lm, n = n0 + j;
            float iv = red[lm * 128 + j]      + bi[n]           + bh[n];
            float fv = red[lm * 128 + 32 + j] + bi[H_ + n]      + bh[H_ + n];
            float gv = red[lm * 128 + 64 + j] + bi[2 * H_ + n]  + bh[2 * H_ + n];
            float ov = red[lm * 128 + 96 + j] + bi[3 * H_ + n]  + bh[3 * H_ + n];
            float cp = cprev[(size_t)m * H_ + n];
            float c2 = sigf(fv) * cp + sigf(iv) * tanhf(gv);
            float h2 = sigf(ov) * tanhf(c2);
            cout[(size_t)m * H_ + n]  = c2;
            hraw[(size_t)m * H_ + n]  = h2;
            houth[(size_t)m * H_ + n] = __float2half_rn(h2);
        }
    } else if (mode == 0) {
        for (int e = tid; e < rpc * 128; e += 256) {
            int lm = e >> 7, c = e & 127;
            int m = sk * rpc + lm;
            float v = tanhf(red[e] + cprev[(size_t)m * H_ + n0 + c]);
            houtf[(size_t)m * H_ + n0 + c] = v;
            houth[(size_t)m * H_ + n0 + c] = __float2half_rn(v);
        }
    } else {   // mode 3
        float* outp = (grp < 8) ? houtf : hraw;
        for (int e = tid; e < rpc * 128; e += 256) {
            int lm = e >> 7, c = e & 127;
            int m = sk * rpc + lm;
            outp[(size_t)m * H_ + nb + c] = red[e];
        }
    }

    // reset counters for the next launch (safe: stream-ordered kernels)
    __syncthreads();
    if (tid == 0) {
        __threadfence();
        int old = atomicAdd(&g_done[grp], 1);
        if (old == split - 1) { g_cnt[grp] = 0; g_done[grp] = 0; __threadfence(); }
    }
}

// ---------------- fused attention: scores + softmax + cvec; grid B, 512 thr ----------------
__global__ __launch_bounds__(512) void attn_kernel(float* __restrict__ attns_t) {
    __shared__ __align__(16) float qs[H_];
    __shared__ float sc[S_];
    __shared__ float sal[S_];
    __shared__ float red8[8];

    const int b = blockIdx.x, tid = threadIdx.x;
    const int w = tid >> 5, l = tid & 31;

    ((float2*)qs)[tid] = ((const float2*)(g_q + (size_t)b * H_))[tid];
    __syncthreads();

    // scores: 16 warps x 8 sequence rows, fp16 ctx, fp32 accumulate
#pragma unroll
    for (int i = 0; i < 8; i++) {
        const int s = w * 8 + i;
        const uint4* row = (const uint4*)(g_ctxh + ((size_t)s * B_ + b) * H_);
        float acc = 0.f;
#pragma unroll
        for (int j = 0; j < 4; j++) {
            uint4 cv = row[j * 32 + l];
            const float* qp = qs + j * 256 + l * 8;
            float2 c0 = __half22float2(*(const __half2*)&cv.x);
            float2 c1 = __half22float2(*(const __half2*)&cv.y);
            float2 c2 = __half22float2(*(const __half2*)&cv.z);
            float2 c3 = __half22float2(*(const __half2*)&cv.w);
            acc += qp[0] * c0.x + qp[1] * c0.y + qp[2] * c1.x + qp[3] * c1.y
                 + qp[4] * c2.x + qp[5] * c2.y + qp[6] * c3.x + qp[7] * c3.y;
        }
#pragma unroll
        for (int o = 16; o > 0; o >>= 1) acc += __shfl_xor_sync(0xFFFFFFFFu, acc, o);
        if (!l) sc[s] = acc;
    }
    __syncthreads();

    // softmax over 128 (first 4 warps)
    float mx = -3.4e38f;
    if (tid < 128) mx = sc[tid];
#pragma unroll
    for (int o = 16; o > 0; o >>= 1) mx = fmaxf(mx, __shfl_xor_sync(0xFFFFFFFFu, mx, o));
    if (tid < 128 && !l) red8[w] = mx;
    __syncthreads();
    const float gmx = fmaxf(fmaxf(red8[0], red8[1]), fmaxf(red8[2], red8[3]));
    float e = 0.f;
    if (tid < 128) { e = expf(sc[tid] - gmx); sal[tid] = e; }
    float se = e;
#pragma unroll
    for (int o = 16; o > 0; o >>= 1) se += __shfl_xor_sync(0xFFFFFFFFu, se, o);
    if (tid < 128 && !l) red8[4 + w] = se;
    __syncthreads();
    const float inv = 1.f / (red8[4] + red8[5] + red8[6] + red8[7]);
    if (tid < 128) {
        float a = sal[tid] * inv;
        sal[tid] = a;
        attns_t[(size_t)b * S_ + tid] = a;
    }
    __syncthreads();

    // cvec from fp16 ctx (L2-hot from score pass), fp32 accumulate; thread -> 2 dims
    float2 acc = make_float2(0.f, 0.f);
#pragma unroll 8
    for (int s = 0; s < S_; s++) {
        const float a = sal[s];
        float2 c = __half22float2(*(const __half2*)(g_ctxh + ((size_t)s * B_ + b) * H_ + tid * 2));
        acc.x += a * c.x;
        acc.y += a * c.y;
    }
    *(__half2*)(g_cvech + (size_t)b * H_ + tid * 2) =
        __floats2half2_rn(acc.x, acc.y);
}

// ---------------- finalize ----------------
__global__ __launch_bounds__(256) void finalize_kernel(float* __restrict__ hF, float* __restrict__ cF) {
    int i = blockIdx.x * blockDim.x + threadIdx.x;
    if (i < BH_) {
        hF[i]       = g_hraw0[i];
        hF[BH_ + i] = g_hraw1[i];
        cF[i]       = g_cb0[i];
        cF[BH_ + i] = g_cb1[i];
    }
}

// ---------------- host launcher ----------------
extern "C" void kernel_launch(void* const* d_in, const int* in_sizes, int n_in,
                              void* d_out, int out_size) {
    const float* inp   = (const float*)d_in[0];
    const float* ctx   = (const float*)d_in[1];
    const float* h0in  = (const float*)d_in[2];
    const float* c0in  = (const float*)d_in[3];
    const float* W_ih0 = (const float*)d_in[4];
    const float* b_ih0 = (const float*)d_in[5];
    const float* W_hh0 = (const float*)d_in[6];
    const float* b_hh0 = (const float*)d_in[7];
    const float* W_ih1 = (const float*)d_in[8];
    const float* b_ih1 = (const float*)d_in[9];
    const float* W_hh1 = (const float*)d_in[10];
    const float* b_hh1 = (const float*)d_in[11];
    const float* W_a   = (const float*)d_in[12];
    const float* W_out = (const float*)d_in[13];

    float* out   = (float*)d_out;
    float* outs  = out;                 // (T,B,H)
    float* hF    = out + TBH_;          // (2,B,H)
    float* cF    = hF + 2 * BH_;        // (2,B,H)
    float* attns = cF + 2 * BH_;        // (T,B,S)

    __half *wih0h, *whh0h, *wih1h, *whh1h, *wah, *wouth;
    __half *inph, *hb0h, *hb1h, *cvech, *feedh, *zerosh;
    float *hraw0, *hraw1, *cb0, *cb1, *q, *oh1;
    cudaGetSymbolAddress((void**)&wih0h, g_wih0h);
    cudaGetSymbolAddress((void**)&whh0h, g_whh0h);
    cudaGetSymbolAddress((void**)&wih1h, g_wih1h);
    cudaGetSymbolAddress((void**)&whh1h, g_whh1h);
    cudaGetSymbolAddress((void**)&wah, g_wah);
    cudaGetSymbolAddress((void**)&wouth, g_wouth);
    cudaGetSymbolAddress((void**)&inph, g_inph);
    cudaGetSymbolAddress((void**)&hb0h, g_hb0h);
    cudaGetSymbolAddress((void**)&hb1h, g_hb1h);
    cudaGetSymbolAddress((void**)&cvech, g_cvech);
    cudaGetSymbolAddress((void**)&feedh, g_feedh);
    cudaGetSymbolAddress((void**)&zerosh, g_zerosh);
    cudaGetSymbolAddress((void**)&hraw0, g_hraw0);
    cudaGetSymbolAddress((void**)&hraw1, g_hraw1);
    cudaGetSymbolAddress((void**)&cb0, g_cb0);
    cudaGetSymbolAddress((void**)&cb1, g_cb1);
    cudaGetSymbolAddress((void**)&q, g_q);
    cudaGetSymbolAddress((void**)&oh1, g_oh1);

    const int smemB = NSTG_ * STGF_H * sizeof(__half);   // 61440
    static int attrSet = 0;
    if (!attrSet) {
        cudaFuncSetAttribute(gemm_kernel, cudaFuncAttributeMaxDynamicSharedMemorySize, smemB);
        attrSet = 1;
    }

    prep_weights<<<2048, 512>>>(W_ih0, W_hh0, W_ih1, W_hh1, W_a, W_out);
    prep_state<<<2048, 512>>>(inp, ctx, h0in, c0in);

    for (int t = 0; t < T_; t++) {
        const __half* fd  = t ? feedh : zerosh;
        const __half* h0p = hb0h + (size_t)(t & 1) * BH_;
        const __half* h1p = hb1h + (size_t)(t & 1) * BH_;
        __half* h0n = hb0h + (size_t)((t + 1) & 1) * BH_;
        __half* h1n = hb1h + (size_t)((t + 1) & 1) * BH_;

        // layer 0: gates = [emb, feed] @ W_ih0^T + h0 @ W_hh0^T  (32 grp x 8 split)
        gemm_kernel<<<32 * 8, 256, smemB>>>(
            inph + (size_t)t * B_ * E_, E_, wih0h,       EH_, 16,
            fd,                         H_, wih0h + E_,  EH_, 32,
            h0p,                        H_, whh0h,       H_,  32,
            1, 8, b_ih0, b_hh0, cb0, cb0, nullptr, h0n, hraw0);

        // layer 1
        gemm_kernel<<<32 * 8, 256, smemB>>>(
            h0n, H_, wih1h, H_, 32,
            h1p, H_, whh1h, H_, 32,
            h0n, H_, whh1h, H_, 0,
            1, 8, b_ih1, b_hh1, cb1, cb1, nullptr, h1n, hraw1);

        // projh: q = h1 @ Wa^T (grp<8) AND oh1 = h1 @ WoutR^T (grp>=8)
        gemm_kernel<<<16 * 8, 256, smemB>>>(
            h1n, H_, wah,          H_,     32,
            h1n, H_, wouth + H_,   2 * H_, 0,
            h1n, H_, wah,          H_,     0,
            3, 8, b_ih0, b_hh0, cb0, cb0, q, nullptr, oh1);

        // fused attention: scores + softmax + cvec (fp16 ctx)
        attn_kernel<<<B_, 512>>>(attns + (size_t)t * B_ * S_);

        // cvproj: attn_h = tanh(cvec @ WoutL^T + oh1) -> outs[t] fp32 + feed half
        gemm_kernel<<<8 * 16, 256, smemB>>>(
            cvech, H_, wouth, 2 * H_, 32,
            cvech, H_, wouth, 2 * H_, 0,
            cvech, H_, wouth, 2 * H_, 0,
            0, 16, b_ih0, b_hh0, oh1, cb0, outs + (size_t)t * B_ * H_, feedh, nullptr);
    }

    finalize_kernel<<<(BH_ + 255) / 256, 256>>>(hF, cF);
}

// round 11
// speedup vs baseline: 1.9253x; 1.1529x over previous
#include <cuda_runtime.h>
#include <cuda_fp16.h>
#include <math.h>
#include <stdint.h>

#define T_  64
#define B_  64
#define S_  128
#define E_  512
#define H_  1024
#define EH_ 1536
#define BH_ (B_*H_)
#define TBH_ ((size_t)T_*B_*H_)
#define NCTA 256
#define NTHR 256

// ---------------- scratch (device globals; zero-init) ----------------
__device__ __align__(16) __half g_wih0h[(size_t)4*H_*EH_];
__device__ __align__(16) __half g_whh0h[(size_t)4*H_*H_];
__device__ __align__(16) __half g_wih1h[(size_t)4*H_*H_];
__device__ __align__(16) __half g_whh1h[(size_t)4*H_*H_];
__device__ __align__(16) __half g_wah[(size_t)H_*H_];
__device__ __align__(16) __half g_wouth[(size_t)H_*2*H_];
__device__ __align__(16) __half g_inph[(size_t)T_*B_*E_];
__device__ __align__(16) __half g_ctxh[(size_t)S_*B_*H_];
__device__ __align__(16) __half g_hb0h[2*BH_];
__device__ __align__(16) __half g_hb1h[2*BH_];
__device__ __align__(16) __half g_cvech[BH_];
__device__ __align__(16) __half g_feedh[BH_];
__device__ __align__(16) __half g_zerosh[BH_];   // never written -> 0
__device__ __align__(16) float g_hraw0[BH_];
__device__ __align__(16) float g_hraw1[BH_];
__device__ __align__(16) float g_cb0[BH_];
__device__ __align__(16) float g_cb1[BH_];
__device__ __align__(16) float g_q[BH_];
__device__ __align__(16) float g_oh1[BH_];
__device__ __align__(16) float g_scores[B_*S_];
__device__ __align__(16) float g_pre[(size_t)T_*B_*4*H_];   // precomputed inp proj (fp32)
__device__ __align__(16) float g_part[(size_t)NCTA*8192];   // split-K partials

// epoch counters (zeroed by prep_state every call)
__device__ unsigned long long c_l0[32], c_l1[32], c_ph[16], c_at[64], c_cv[8];
__device__ unsigned long long c_p0, c_p1, c_p2, c_p3, c_p4;

__device__ __forceinline__ float sigf(float x) { return 1.f / (1.f + expf(-x)); }

__device__ __forceinline__ void cp16(void* dst, const void* src) {
    unsigned s = (unsigned)__cvta_generic_to_shared(dst);
    asm volatile("cp.async.cg.shared.global [%0], [%1], 16;\n" :: "r"(s), "l"(src));
}

__device__ __forceinline__ void mma16(float* c, const uint32_t* a, const uint32_t* b) {
    asm volatile(
        "mma.sync.aligned.m16n8k16.row.col.f32.f16.f16.f32 "
        "{%0,%1,%2,%3}, {%4,%5,%6,%7}, {%8,%9}, {%0,%1,%2,%3};\n"
        : "+f"(c[0]), "+f"(c[1]), "+f"(c[2]), "+f"(c[3])
        : "r"(a[0]), "r"(a[1]), "r"(a[2]), "r"(a[3]), "r"(b[0]), "r"(b[1]));
}

__device__ __forceinline__ void arrive(unsigned long long* c) {
    __threadfence();
    __syncthreads();
    if (threadIdx.x == 0) atomicAdd(c, 1ULL);
}
__device__ __forceinline__ void wait_ge(unsigned long long* c, unsigned long long tgt) {
    if (threadIdx.x == 0) {
        unsigned long long v;
        do {
            asm volatile("ld.acquire.gpu.u64 %0, [%1];" : "=l"(v) : "l"(c));
        } while (v < tgt);
    }
    __syncthreads();
}

// ---------------- prep kernels ----------------
__global__ __launch_bounds__(512) void prep_weights(
    const float* __restrict__ wih0, const float* __restrict__ whh0,
    const float* __restrict__ wih1, const float* __restrict__ whh1,
    const float* __restrict__ wa,   const float* __restrict__ wout) {
    const size_t n0 = (size_t)4 * H_ * EH_;
    const size_t n1 = (size_t)4 * H_ * H_;
    const size_t n2 = (size_t)H_ * H_;
    const size_t n3 = (size_t)H_ * 2 * H_;
    const size_t tot = n0 + 3 * n1 + n2 + n3;
    for (size_t i = (size_t)blockIdx.x * blockDim.x + threadIdx.x; i < tot;
         i += (size_t)gridDim.x * blockDim.x) {
        size_t j = i; float v; __half* d;
        if (j < n0) { v = wih0[j]; d = g_wih0h + j; }
        else { j -= n0;
        if (j < n1) { v = whh0[j]; d = g_whh0h + j; }
        else { j -= n1;
        if (j < n1) { v = wih1[j]; d = g_wih1h + j; }
        else { j -= n1;
        if (j < n1) { v = whh1[j]; d = g_whh1h + j; }
        else { j -= n1;
        if (j < n2) { v = wa[j];   d = g_wah + j; }
        else { j -= n2; v = wout[j]; d = g_wouth + j; } } } } }
        *d = __float2half_rn(v);
    }
}

__global__ __launch_bounds__(512) void prep_state(const float* __restrict__ inp,
                                                  const float* __restrict__ ctx,
                                                  const float* __restrict__ h0,
                                                  const float* __restrict__ c0) {
    if (blockIdx.x == 0) {
        int t = threadIdx.x;
        if (t < 32) { c_l0[t] = 0; c_l1[t] = 0; }
        if (t < 16) c_ph[t] = 0;
        if (t < 64) c_at[t] = 0;
        if (t < 8)  c_cv[t] = 0;
        if (t == 0) { c_p0 = 0; c_p1 = 0; c_p2 = 0; c_p3 = 0; c_p4 = 0; }
    }
    const size_t ninp = (size_t)T_ * B_ * E_;
    const size_t nctx = (size_t)S_ * B_ * H_;
    const size_t tot = ninp + nctx + 2 * BH_;
    for (size_t i = (size_t)blockIdx.x * blockDim.x + threadIdx.x; i < tot;
         i += (size_t)gridDim.x * blockDim.x) {
        if (i < ninp) { g_inph[i] = __float2half_rn(inp[i]); continue; }
        size_t j = i - ninp;
        if (j < nctx) { g_ctxh[j] = __float2half_rn(ctx[j]); continue; }
        j -= nctx;
        if (j < BH_) { g_hb0h[j] = __float2half_rn(h0[j]); g_cb0[j] = c0[j]; }
        else { j -= BH_; g_hb1h[j] = __float2half_rn(h0[BH_ + j]); g_cb1[j] = c0[BH_ + j]; }
    }
}

// ---------------- GEMM machinery ----------------
#define STRDH 40                 // halves per smem row (32 + 8 pad)
#define STGA_H (64*STRDH)        // A region: 2560 halves
#define STGF_H (192*STRDH)       // stage: 7680 halves = 15360 B
#define NSTG_ 4

struct Seg { const __half* A; int lda; const __half* W; int ldw; int kt; };

__device__ __forceinline__ void gemm_ml(
    Seg s0, Seg s1, int cpk, int cbase,
    int rA, int cA, const int rW[2], const int cW[2], const int wrW[2],
    __half* smh, float acc[2][4][4], int wm, int wn, int g8, int tg)
{
    __syncthreads();   // protect smem ring reuse across phases

#pragma unroll
    for (int mi = 0; mi < 2; mi++)
#pragma unroll
        for (int ni = 0; ni < 4; ni++)
#pragma unroll
            for (int e = 0; e < 4; e++) acc[mi][ni][e] = 0.f;

    auto issue = [&](int c, int buf) {
        const __half* Ab; const __half* Wb; int la, lw, ko;
        if (c < s0.kt) { Ab = s0.A; Wb = s0.W; la = s0.lda; lw = s0.ldw; ko = c * 32; }
        else           { Ab = s1.A; Wb = s1.W; la = s1.lda; lw = s1.ldw; ko = (c - s0.kt) * 32; }
        __half* st = smh + buf * STGF_H;
        cp16(st + rA * STRDH + cA, Ab + (size_t)rA * la + ko + cA);
#pragma unroll
        for (int j = 0; j < 2; j++)
            cp16(st + STGA_H + rW[j] * STRDH + cW[j], Wb + (size_t)wrW[j] * lw + ko + cW[j]);
        asm volatile("cp.async.commit_group;\n");
    };

    const int npro = cpk < 3 ? cpk : 3;
    for (int s = 0; s < npro; s++) issue(cbase + s, s);

    for (int i = 0; i < cpk; i++) {
        const int rem = cpk - 1 - i;
        if (rem >= 2)      asm volatile("cp.async.wait_group 2;\n");
        else if (rem == 1) asm volatile("cp.async.wait_group 1;\n");
        else               asm volatile("cp.async.wait_group 0;\n");
        __syncthreads();
        if (i + 3 < cpk) issue(cbase + i + 3, (i + 3) & 3);

        const __half* stg = smh + (i & 3) * STGF_H;
        const uint32_t* pA = (const uint32_t*)stg + (wm * 32 + g8) * 20 + tg;
        const uint32_t* pB = (const uint32_t*)(stg + STGA_H) + (wn * 32 + g8) * 20 + tg;
#pragma unroll
        for (int kk = 0; kk < 2; kk++) {
            const int ko = kk * 8;
            uint32_t a0[4], a1[4], b[4][2];
            a0[0] = pA[ko];               a0[1] = pA[8 * 20 + ko];
            a0[2] = pA[ko + 4];           a0[3] = pA[8 * 20 + ko + 4];
            a1[0] = pA[16 * 20 + ko];     a1[1] = pA[24 * 20 + ko];
            a1[2] = pA[16 * 20 + ko + 4]; a1[3] = pA[24 * 20 + ko + 4];
#pragma unroll
            for (int ni = 0; ni < 4; ni++) {
                b[ni][0] = pB[ni * 8 * 20 + ko];
                b[ni][1] = pB[ni * 8 * 20 + ko + 4];
            }
#pragma unroll
            for (int ni = 0; ni < 4; ni++) {
                mma16(acc[0][ni], a0, b[ni]);
                mma16(acc[1][ni], a1, b[ni]);
            }
        }
    }
}

__device__ __forceinline__ void store_partial(float acc[2][4][4], int wm, int wn, int g8, int tg) {
    float* pp = g_part + (size_t)blockIdx.x * 8192;
#pragma unroll
    for (int mi = 0; mi < 2; mi++)
#pragma unroll
        for (int ni = 0; ni < 4; ni++) {
            int r = wm * 32 + mi * 16 + g8, c = wn * 32 + ni * 8 + tg * 2;
            *(float2*)(pp + r * 128 + c)       = make_float2(acc[mi][ni][0], acc[mi][ni][1]);
            *(float2*)(pp + (r + 8) * 128 + c) = make_float2(acc[mi][ni][2], acc[mi][ni][3]);
        }
}

// reduce this CTA's row slice of its group's partials (L1-bypassing loads)
__device__ __forceinline__ void reduce_slice(float* red, int grp, int split, int sk, int rpc) {
    const float* pb = g_part + (size_t)(grp * split) * 8192 + sk * rpc * 128;
    for (int e4 = threadIdx.x; e4 < rpc * 32; e4 += NTHR) {
        float4 s = __ldcv((const float4*)(pb + e4 * 4));
        for (int p = 1; p < split; p++) {
            float4 v = __ldcv((const float4*)(pb + (size_t)p * 8192 + e4 * 4));
            s.x += v.x; s.y += v.y; s.z += v.z; s.w += v.w;
        }
        *(float4*)(red + e4 * 4) = s;
    }
    __syncthreads();
}

// ---------------- persistent megakernel ----------------
__global__ void __launch_bounds__(NTHR, 2) mega_kernel(
    const float* __restrict__ bi0, const float* __restrict__ bh0,
    const float* __restrict__ bi1, const float* __restrict__ bh1,
    float* __restrict__ outs, float* __restrict__ attns,
    float* __restrict__ hF, float* __restrict__ cF)
{
    extern __shared__ __align__(16) __half smh[];
    const int tid = threadIdx.x;
    const int w = tid >> 5, lane = tid & 31;
    const int wm = w >> 2, wn = w & 3;
    const int g8 = lane >> 2, tg = lane & 3;
    const int cta = blockIdx.x;

    // copy maps
    const int rA = tid >> 2, cA = (tid & 3) * 8;
    int rW[2], cW[2];
#pragma unroll
    for (int j = 0; j < 2; j++) {
        int qk = j * 256 + tid;
        rW[j] = qk >> 2; cW[j] = (qk & 3) * 8;
    }

    float acc[2][4][4];

    // ---- phase -1: precompute inp @ Wih0_left^T for all t ----
    for (int tile = cta; tile < 64 * 32; tile += NCTA) {
        const int t = tile >> 5, grp = tile & 31;
        const int n0 = grp * 32;
        int wrW[2];
#pragma unroll
        for (int j = 0; j < 2; j++) wrW[j] = (rW[j] >> 5) * H_ + n0 + (rW[j] & 31);
        Seg s{g_inph + (size_t)t * B_ * E_, E_, g_wih0h, EH_, 16};
        gemm_ml(s, s, 16, 0, rA, cA, rW, cW, wrW, smh, acc, wm, wn, g8, tg);
        float* dst = g_pre + (size_t)t * B_ * 4 * H_;
#pragma unroll
        for (int mi = 0; mi < 2; mi++)
#pragma unroll
            for (int ni = 0; ni < 4; ni++) {
                int r = wm * 32 + mi * 16 + g8, cc = wn * 32 + ni * 8 + tg * 2;
                int n = (cc >> 5) * H_ + n0 + (cc & 31);
                *(float2*)(dst + (size_t)r * 4096 + n)       = make_float2(acc[mi][ni][0], acc[mi][ni][1]);
                *(float2*)(dst + (size_t)(r + 8) * 4096 + n) = make_float2(acc[mi][ni][2], acc[mi][ni][3]);
            }
    }
    arrive(&c_p4);   // precompute completion counts toward step-0 gate

    // per-phase CTA roles
    const int grpL = cta >> 3, skL = cta & 7;     // lstm: 32 grp x 8
    const int grpP = cta >> 4, skP = cta & 15;    // projh: 16 grp x 16
    const int grpC = cta >> 5, skC = cta & 31;    // cvproj: 8 grp x 32

    for (int t = 0; t < T_; t++) {
        const __half* fd  = t ? g_feedh : g_zerosh;
        const __half* h0p = g_hb0h + (size_t)(t & 1) * BH_;
        const __half* h1p = g_hb1h + (size_t)(t & 1) * BH_;
        __half* h0n = g_hb0h + (size_t)((t + 1) & 1) * BH_;
        __half* h1n = g_hb1h + (size_t)((t + 1) & 1) * BH_;
        float* red = (float*)smh;

        // ---- P0: lstm0 ----
        wait_ge(&c_p4, (unsigned long long)(t + 1) * 256);
        {
            const int n0 = grpL * 32;
            int wrW[2];
#pragma unroll
            for (int j = 0; j < 2; j++) wrW[j] = (rW[j] >> 5) * H_ + n0 + (rW[j] & 31);
            Seg s0{fd, H_, g_wih0h + E_, EH_, 32};
            Seg s1{h0p, H_, g_whh0h, H_, 32};
            gemm_ml(s0, s1, 8, skL * 8, rA, cA, rW, cW, wrW, smh, acc, wm, wn, g8, tg);
            store_partial(acc, wm, wn, g8, tg);
            arrive(&c_l0[grpL]);
            wait_ge(&c_l0[grpL], (unsigned long long)(t + 1) * 8);
            reduce_slice(red, grpL, 8, skL, 8);
            const float* pre = g_pre + (size_t)t * B_ * 4 * H_;
            for (int e = tid; e < 8 * 32; e += NTHR) {
                int lm = e >> 5, j = e & 31;
                int m = skL * 8 + lm, n = n0 + j;
                float iv = red[lm * 128 + j]      + bi0[n]          + bh0[n]          + pre[(size_t)m * 4096 + n];
                float fv = red[lm * 128 + 32 + j] + bi0[H_ + n]     + bh0[H_ + n]     + pre[(size_t)m * 4096 + H_ + n];
                float gv = red[lm * 128 + 64 + j] + bi0[2 * H_ + n] + bh0[2 * H_ + n] + pre[(size_t)m * 4096 + 2 * H_ + n];
                float ov = red[lm * 128 + 96 + j] + bi0[3 * H_ + n] + bh0[3 * H_ + n] + pre[(size_t)m * 4096 + 3 * H_ + n];
                float cp = g_cb0[(size_t)m * H_ + n];
                float c2 = sigf(fv) * cp + sigf(iv) * tanhf(gv);
                float h2 = sigf(ov) * tanhf(c2);
                g_cb0[(size_t)m * H_ + n]  = c2;
                g_hraw0[(size_t)m * H_ + n] = h2;
                h0n[(size_t)m * H_ + n] = __float2half_rn(h2);
            }
            arrive(&c_p0);
        }

        // ---- P1: lstm1 ----
        wait_ge(&c_p0, (unsigned long long)(t + 1) * 256);
        {
            const int n0 = grpL * 32;
            int wrW[2];
#pragma unroll
            for (int j = 0; j < 2; j++) wrW[j] = (rW[j] >> 5) * H_ + n0 + (rW[j] & 31);
            Seg s0{h0n, H_, g_wih1h, H_, 32};
            Seg s1{h1p, H_, g_whh1h, H_, 32};
            gemm_ml(s0, s1, 8, skL * 8, rA, cA, rW, cW, wrW, smh, acc, wm, wn, g8, tg);
            store_partial(acc, wm, wn, g8, tg);
            arrive(&c_l1[grpL]);
            wait_ge(&c_l1[grpL], (unsigned long long)(t + 1) * 8);
            reduce_slice(red, grpL, 8, skL, 8);
            for (int e = tid; e < 8 * 32; e += NTHR) {
                int lm = e >> 5, j = e & 31;
                int m = skL * 8 + lm, n = n0 + j;
                float iv = red[lm * 128 + j]      + bi1[n]          + bh1[n];
                float fv = red[lm * 128 + 32 + j] + bi1[H_ + n]     + bh1[H_ + n];
                float gv = red[lm * 128 + 64 + j] + bi1[2 * H_ + n] + bh1[2 * H_ + n];
                float ov = red[lm * 128 + 96 + j] + bi1[3 * H_ + n] + bh1[3 * H_ + n];
                float cp = g_cb1[(size_t)m * H_ + n];
                float c2 = sigf(fv) * cp + sigf(iv) * tanhf(gv);
                float h2 = sigf(ov) * tanhf(c2);
                g_cb1[(size_t)m * H_ + n]  = c2;
                g_hraw1[(size_t)m * H_ + n] = h2;
                h1n[(size_t)m * H_ + n] = __float2half_rn(h2);
            }
            arrive(&c_p1);
        }

        // ---- P2: projh (q | oh1) ----
        wait_ge(&c_p1, (unsigned long long)(t + 1) * 256);
        {
            const __half* W; int ldw, nb;
            if (grpP < 8) { W = g_wah;        ldw = H_;     nb = grpP * 128; }
            else          { W = g_wouth + H_; ldw = 2 * H_; nb = (grpP - 8) * 128; }
            int wrW[2];
#pragma unroll
            for (int j = 0; j < 2; j++) wrW[j] = nb + rW[j];
            Seg s0{h1n, H_, W, ldw, 32};
            gemm_ml(s0, s0, 2, skP * 2, rA, cA, rW, cW, wrW, smh, acc, wm, wn, g8, tg);
            store_partial(acc, wm, wn, g8, tg);
            arrive(&c_ph[grpP]);
            wait_ge(&c_ph[grpP], (unsigned long long)(t + 1) * 16);
            reduce_slice(red, grpP, 16, skP, 4);
            float* outp = (grpP < 8) ? g_q : g_oh1;
            for (int e = tid; e < 4 * 128; e += NTHR) {
                int lm = e >> 7, c = e & 127;
                int m = skP * 4 + lm;
                outp[(size_t)m * H_ + nb + c] = red[e];
            }
            arrive(&c_p2);
        }

        // ---- P3: attention (CTAs 0..127) ----
        if (cta < 128) {
            wait_ge(&c_p2, (unsigned long long)(t + 1) * 256);
            const int b = cta >> 1, part = cta & 1;
            float* qs   = (float*)smh;
            float* sc   = qs + H_;
            float* sal  = sc + S_;
            float* red8 = sal + S_;
            __syncthreads();   // smem reuse
            ((float4*)qs)[tid] = __ldcv(((const float4*)(g_q + (size_t)b * H_)) + tid);
            __syncthreads();
            const int sbase = part * 64;
#pragma unroll
            for (int i = 0; i < 8; i++) {
                const int s = sbase + w * 8 + i;
                const uint4* row = (const uint4*)(g_ctxh + ((size_t)s * B_ + b) * H_);
                float a2 = 0.f;
#pragma unroll
                for (int j = 0; j < 4; j++) {
                    uint4 cv = row[j * 32 + lane];
                    const float* qp = qs + j * 256 + lane * 8;
                    float2 c0 = __half22float2(*(const __half2*)&cv.x);
                    float2 c1 = __half22float2(*(const __half2*)&cv.y);
                    float2 c2 = __half22float2(*(const __half2*)&cv.z);
                    float2 c3 = __half22float2(*(const __half2*)&cv.w);
                    a2 += qp[0] * c0.x + qp[1] * c0.y + qp[2] * c1.x + qp[3] * c1.y
                        + qp[4] * c2.x + qp[5] * c2.y + qp[6] * c3.x + qp[7] * c3.y;
                }
#pragma unroll
                for (int o = 16; o > 0; o >>= 1) a2 += __shfl_xor_sync(0xFFFFFFFFu, a2, o);
                if (!lane) g_scores[b * S_ + s] = a2;
            }
            arrive(&c_at[b]);
            wait_ge(&c_at[b], (unsigned long long)(t + 1) * 2);
            if (tid < 128) sc[tid] = __ldcv(g_scores + b * S_ + tid);
            __syncthreads();
            float mx = -3.4e38f;
            if (tid < 128) mx = sc[tid];
#pragma unroll
            for (int o = 16; o > 0; o >>= 1) mx = fmaxf(mx, __shfl_xor_sync(0xFFFFFFFFu, mx, o));
            if (tid < 128 && !lane) red8[w] = mx;
            __syncthreads();
            const float gmx = fmaxf(fmaxf(red8[0], red8[1]), fmaxf(red8[2], red8[3]));
            float e = 0.f;
            if (tid < 128) { e = expf(sc[tid] - gmx); sal[tid] = e; }
            float se = e;
#pragma unroll
            for (int o = 16; o > 0; o >>= 1) se += __shfl_xor_sync(0xFFFFFFFFu, se, o);
            if (tid < 128 && !lane) red8[4 + w] = se;
            __syncthreads();
            const float inv = 1.f / (red8[4] + red8[5] + red8[6] + red8[7]);
            if (tid < 128) {
                float a = sal[tid] * inv;
                sal[tid] = a;
                if (part == 0) attns[(size_t)t * B_ * S_ + b * S_ + tid] = a;
            }
            __syncthreads();
            const int d0 = part * 512 + tid * 2;
            float2 a2 = make_float2(0.f, 0.f);
#pragma unroll 8
            for (int s = 0; s < S_; s++) {
                const float a = sal[s];
                float2 c = __half22float2(*(const __half2*)(g_ctxh + ((size_t)s * B_ + b) * H_ + d0));
                a2.x += a * c.x;
                a2.y += a * c.y;
            }
            *(__half2*)(g_cvech + (size_t)b * H_ + d0) = __floats2half2_rn(a2.x, a2.y);
            arrive(&c_p3);
        }
        wait_ge(&c_p3, (unsigned long long)(t + 1) * 128);

        // ---- P4: cvproj ----
        {
            const int nb = grpC * 128;
            int wrW[2];
#pragma unroll
            for (int j = 0; j < 2; j++) wrW[j] = nb + rW[j];
            Seg s0{g_cvech, H_, g_wouth, 2 * H_, 32};
            gemm_ml(s0, s0, 1, skC, rA, cA, rW, cW, wrW, smh, acc, wm, wn, g8, tg);
            store_partial(acc, wm, wn, g8, tg);
            arrive(&c_cv[grpC]);
            wait_ge(&c_cv[grpC], (unsigned long long)(t + 1) * 32);
            reduce_slice(red, grpC, 32, skC, 2);
            for (int e = tid; e < 2 * 128; e += NTHR) {
                int lm = e >> 7, c = e & 127;
                int m = skC * 2 + lm;
                float v = tanhf(red[e] + __ldcv(g_oh1 + (size_t)m * H_ + nb + c));
                outs[(size_t)t * B_ * H_ + (size_t)m * H_ + nb + c] = v;
                g_feedh[(size_t)m * H_ + nb + c] = __float2half_rn(v);
            }
            arrive(&c_p4);
        }
    }

    // ---- finalize ----
    wait_ge(&c_p4, (unsigned long long)(T_ + 1) * 256);
    {
        const int i = cta * NTHR + tid;   // exactly BH_
        hF[i]       = __ldcv(g_hraw0 + i);
        hF[BH_ + i] = __ldcv(g_hraw1 + i);
        cF[i]       = __ldcv(g_cb0 + i);
        cF[BH_ + i] = __ldcv(g_cb1 + i);
    }
}

// ---------------- host launcher ----------------
extern "C" void kernel_launch(void* const* d_in, const int* in_sizes, int n_in,
                              void* d_out, int out_size) {
    const float* inp   = (const float*)d_in[0];
    const float* ctx   = (const float*)d_in[1];
    const float* h0in  = (const float*)d_in[2];
    const float* c0in  = (const float*)d_in[3];
    const float* W_ih0 = (const float*)d_in[4];
    const float* b_ih0 = (const float*)d_in[5];
    const float* W_hh0 = (const float*)d_in[6];
    const float* b_hh0 = (const float*)d_in[7];
    const float* W_ih1 = (const float*)d_in[8];
    const float* b_ih1 = (const float*)d_in[9];
    const float* W_hh1 = (const float*)d_in[10];
    const float* b_hh1 = (const float*)d_in[11];
    const float* W_a   = (const float*)d_in[12];
    const float* W_out = (const float*)d_in[13];

    float* out   = (float*)d_out;
    float* outs  = out;                 // (T,B,H)
    float* hF    = out + TBH_;          // (2,B,H)
    float* cF    = hF + 2 * BH_;        // (2,B,H)
    float* attns = cF + 2 * BH_;        // (T,B,S)

    const int smemB = NSTG_ * STGF_H * sizeof(__half);   // 61440
    static int attrSet = 0;
    if (!attrSet) {
        cudaFuncSetAttribute(mega_kernel, cudaFuncAttributeMaxDynamicSharedMemorySize, smemB);
        attrSet = 1;
    }

    prep_weights<<<2048, 512>>>(W_ih0, W_hh0, W_ih1, W_hh1, W_a, W_out);
    prep_state<<<2048, 512>>>(inp, ctx, h0in, c0in);
    mega_kernel<<<NCTA, NTHR, smemB>>>(b_ih0, b_hh0, b_ih1, b_hh1, outs, attns, hF, cF);
}